// round 1
// baseline (speedup 1.0000x reference)
#include <cuda_runtime.h>

#define BB 2
#define SS 2048
#define HH 768
#define NH 12
#define DD 64
#define BH (BB*NH)                 // 24
#define M_PROJ (BB*SS)             // 4096
#define OUT_ELEMS (BB*SS*HH)       // 3145728
#define ATTN_ELEMS ((size_t)BB*NH*SS*SS) // 100663296
#define NEGV (-1e32f)

// ---- scratch (device globals: no allocation allowed) ----
__device__ float g_qh[BB*NH*SS*DD];     // [B,H,S,D]
__device__ float g_kh[BB*NH*SS*DD];
__device__ float g_vh[BB*NH*SS*DD];
__device__ float g_ctx[BB*SS*HH];       // merged heads [B,S,H*D]
__device__ float g_attn_scratch[BB*NH*SS*SS]; // fallback if attn not in d_out

// ============================================================
// Kernel 1: fused QKV projections.
// Y[m][n] = sum_k X[m][k] * W[n][k] + b[n], written head-split [B,H,S,D].
// M=4096, N=768, K=768. Tiles 64x64x16, 256 threads, 4x4 micro-tile.
// ============================================================
__global__ void proj_qkv_kernel(const float* __restrict__ q,
                                const float* __restrict__ k,
                                const float* __restrict__ v,
                                const float* __restrict__ Wq, const float* __restrict__ bq,
                                const float* __restrict__ Wk, const float* __restrict__ bk,
                                const float* __restrict__ Wv, const float* __restrict__ bv) {
    const float* X; const float* W; const float* bias; float* Y;
    if (blockIdx.z == 0)      { X = q; W = Wq; bias = bq; Y = g_qh; }
    else if (blockIdx.z == 1) { X = k; W = Wk; bias = bk; Y = g_kh; }
    else                      { X = v; W = Wv; bias = bv; Y = g_vh; }

    __shared__ float As[16][65];  // [kk][m]
    __shared__ float Bs[16][65];  // [kk][n]
    int tid = threadIdx.x;
    int tx = tid & 15, ty = tid >> 4;
    int m0 = blockIdx.y * 64, n0 = blockIdx.x * 64;

    float acc[4][4] = {};
    for (int k0 = 0; k0 < HH; k0 += 16) {
        #pragma unroll
        for (int i = 0; i < 4; i++) {
            int idx = tid + 256 * i;
            int r = idx >> 4, c = idx & 15;
            As[c][r] = X[(size_t)(m0 + r) * HH + k0 + c];
            Bs[c][r] = W[(size_t)(n0 + r) * HH + k0 + c];
        }
        __syncthreads();
        #pragma unroll
        for (int kk = 0; kk < 16; kk++) {
            float a[4], b[4];
            #pragma unroll
            for (int i = 0; i < 4; i++) a[i] = As[kk][ty * 4 + i];
            #pragma unroll
            for (int j = 0; j < 4; j++) b[j] = Bs[kk][tx * 4 + j];
            #pragma unroll
            for (int i = 0; i < 4; i++)
                #pragma unroll
                for (int j = 0; j < 4; j++) acc[i][j] += a[i] * b[j];
        }
        __syncthreads();
    }
    #pragma unroll
    for (int i = 0; i < 4; i++) {
        int m = m0 + ty * 4 + i;
        int b_idx = m / SS, s = m % SS;
        #pragma unroll
        for (int j = 0; j < 4; j++) {
            int n = n0 + tx * 4 + j;
            int h = n >> 6, d = n & 63;
            Y[(((size_t)b_idx * NH + h) * SS + s) * DD + d] = acc[i][j] + bias[n];
        }
    }
}

// ============================================================
// Kernel 2: scores = (qh @ kh^T) / 8, masked. Per (b,h): M=N=2048, K=64.
// ============================================================
__global__ void scores_kernel(const int* __restrict__ mask, float* __restrict__ attn) {
    int bh = blockIdx.z;
    int b_idx = bh / NH;
    const float* A = g_qh + (size_t)bh * SS * DD;
    const float* Bm = g_kh + (size_t)bh * SS * DD;

    __shared__ float As[16][65];
    __shared__ float Bs[16][65];
    int tid = threadIdx.x;
    int tx = tid & 15, ty = tid >> 4;
    int m0 = blockIdx.y * 64, n0 = blockIdx.x * 64;

    float acc[4][4] = {};
    for (int k0 = 0; k0 < DD; k0 += 16) {
        #pragma unroll
        for (int i = 0; i < 4; i++) {
            int idx = tid + 256 * i;
            int r = idx >> 4, c = idx & 15;
            As[c][r] = A[(size_t)(m0 + r) * DD + k0 + c];
            Bs[c][r] = Bm[(size_t)(n0 + r) * DD + k0 + c];
        }
        __syncthreads();
        #pragma unroll
        for (int kk = 0; kk < 16; kk++) {
            float a[4], b[4];
            #pragma unroll
            for (int i = 0; i < 4; i++) a[i] = As[kk][ty * 4 + i];
            #pragma unroll
            for (int j = 0; j < 4; j++) b[j] = Bs[kk][tx * 4 + j];
            #pragma unroll
            for (int i = 0; i < 4; i++)
                #pragma unroll
                for (int j = 0; j < 4; j++) acc[i][j] += a[i] * b[j];
        }
        __syncthreads();
    }
    #pragma unroll
    for (int j = 0; j < 4; j++) {
        int n = n0 + tx * 4 + j;
        int msk = mask[b_idx * SS + n];
        #pragma unroll
        for (int i = 0; i < 4; i++) {
            int m = m0 + ty * 4 + i;
            float val = msk ? NEGV : acc[i][j] * 0.125f;
            attn[((size_t)bh * SS + m) * SS + n] = val;
        }
    }
}

// ============================================================
// Kernel 3: row softmax in place. One block per row (2048 cols, 256 thr).
// ============================================================
__global__ void softmax_kernel(float* __restrict__ attn) {
    size_t row = blockIdx.x;
    float* p = attn + row * SS;
    int tid = threadIdx.x;
    int lane = tid & 31, warp = tid >> 5;

    float vals[8];
    float mx = -INFINITY;
    #pragma unroll
    for (int i = 0; i < 8; i++) {
        vals[i] = p[tid + 256 * i];
        mx = fmaxf(mx, vals[i]);
    }
    __shared__ float red[8];
    #pragma unroll
    for (int o = 16; o; o >>= 1) mx = fmaxf(mx, __shfl_xor_sync(0xFFFFFFFFu, mx, o));
    if (lane == 0) red[warp] = mx;
    __syncthreads();
    mx = red[0];
    #pragma unroll
    for (int w = 1; w < 8; w++) mx = fmaxf(mx, red[w]);
    __syncthreads();

    float sum = 0.f;
    #pragma unroll
    for (int i = 0; i < 8; i++) {
        vals[i] = __expf(vals[i] - mx);
        sum += vals[i];
    }
    #pragma unroll
    for (int o = 16; o; o >>= 1) sum += __shfl_xor_sync(0xFFFFFFFFu, sum, o);
    if (lane == 0) red[warp] = sum;
    __syncthreads();
    sum = red[0];
    #pragma unroll
    for (int w = 1; w < 8; w++) sum += red[w];
    float inv = 1.0f / sum;
    #pragma unroll
    for (int i = 0; i < 8; i++) p[tid + 256 * i] = vals[i] * inv;
}

// ============================================================
// Kernel 4: ctx = attn @ vh. Per (b,h): M=2048, N=64, K=2048.
// Writes merged-head layout [B,S,H*D].
// ============================================================
__global__ void av_kernel(const float* __restrict__ attn) {
    int bh = blockIdx.z;
    int b_idx = bh / NH, h = bh % NH;
    const float* A = attn + (size_t)bh * SS * SS;   // [m][k], lda=SS
    const float* V = g_vh + (size_t)bh * SS * DD;   // [k][d]

    __shared__ float As[16][65];  // [kk][m]
    __shared__ float Bs[16][65];  // [kk][n(d)]
    int tid = threadIdx.x;
    int tx = tid & 15, ty = tid >> 4;
    int m0 = blockIdx.y * 64;

    float acc[4][4] = {};
    for (int k0 = 0; k0 < SS; k0 += 16) {
        #pragma unroll
        for (int i = 0; i < 4; i++) {
            int idx = tid + 256 * i;
            int r = idx >> 4, c = idx & 15;
            As[c][r] = A[(size_t)(m0 + r) * SS + k0 + c];
            int kk = idx >> 6, j = idx & 63;
            Bs[kk][j] = V[(size_t)(k0 + kk) * DD + j];
        }
        __syncthreads();
        #pragma unroll
        for (int kk = 0; kk < 16; kk++) {
            float a[4], b[4];
            #pragma unroll
            for (int i = 0; i < 4; i++) a[i] = As[kk][ty * 4 + i];
            #pragma unroll
            for (int j = 0; j < 4; j++) b[j] = Bs[kk][tx * 4 + j];
            #pragma unroll
            for (int i = 0; i < 4; i++)
                #pragma unroll
                for (int j = 0; j < 4; j++) acc[i][j] += a[i] * b[j];
        }
        __syncthreads();
    }
    #pragma unroll
    for (int i = 0; i < 4; i++) {
        int m = m0 + ty * 4 + i;
        #pragma unroll
        for (int j = 0; j < 4; j++) {
            int n = tx * 4 + j;   // d index
            g_ctx[((size_t)b_idx * SS + m) * HH + h * 64 + n] = acc[i][j];
        }
    }
}

// ============================================================
// Kernel 5: out = ctx @ Wm^T + bm. M=4096, N=768, K=768, row-major out.
// ============================================================
__global__ void out_proj_kernel(const float* __restrict__ Wm,
                                const float* __restrict__ bm,
                                float* __restrict__ out) {
    __shared__ float As[16][65];
    __shared__ float Bs[16][65];
    int tid = threadIdx.x;
    int tx = tid & 15, ty = tid >> 4;
    int m0 = blockIdx.y * 64, n0 = blockIdx.x * 64;

    float acc[4][4] = {};
    for (int k0 = 0; k0 < HH; k0 += 16) {
        #pragma unroll
        for (int i = 0; i < 4; i++) {
            int idx = tid + 256 * i;
            int r = idx >> 4, c = idx & 15;
            As[c][r] = g_ctx[(size_t)(m0 + r) * HH + k0 + c];
            Bs[c][r] = Wm[(size_t)(n0 + r) * HH + k0 + c];
        }
        __syncthreads();
        #pragma unroll
        for (int kk = 0; kk < 16; kk++) {
            float a[4], b[4];
            #pragma unroll
            for (int i = 0; i < 4; i++) a[i] = As[kk][ty * 4 + i];
            #pragma unroll
            for (int j = 0; j < 4; j++) b[j] = Bs[kk][tx * 4 + j];
            #pragma unroll
            for (int i = 0; i < 4; i++)
                #pragma unroll
                for (int j = 0; j < 4; j++) acc[i][j] += a[i] * b[j];
        }
        __syncthreads();
    }
    #pragma unroll
    for (int i = 0; i < 4; i++) {
        int m = m0 + ty * 4 + i;
        #pragma unroll
        for (int j = 0; j < 4; j++) {
            int n = n0 + tx * 4 + j;
            out[(size_t)m * HH + n] = acc[i][j] + bm[n];
        }
    }
}

// ============================================================
// Host launcher
// ============================================================
extern "C" void kernel_launch(void* const* d_in, const int* in_sizes, int n_in,
                              void* d_out, int out_size) {
    const float* v    = (const float*)d_in[0];
    const float* k    = (const float*)d_in[1];
    const float* q    = (const float*)d_in[2];
    const int*   mask = (const int*)  d_in[3];
    const float* Wv   = (const float*)d_in[4];
    const float* bv   = (const float*)d_in[5];
    const float* Wk   = (const float*)d_in[6];
    const float* bk   = (const float*)d_in[7];
    const float* Wq   = (const float*)d_in[8];
    const float* bq   = (const float*)d_in[9];
    const float* Wm   = (const float*)d_in[10];
    const float* bm   = (const float*)d_in[11];
    float* out = (float*)d_out;

    // attn output: reference returns (out, attn). If out_size covers both,
    // attn lives in d_out right after out; otherwise use device scratch.
    float* attn;
    if ((size_t)out_size >= (size_t)OUT_ELEMS + ATTN_ELEMS) {
        attn = out + OUT_ELEMS;
    } else {
        void* p = nullptr;
        cudaGetSymbolAddress(&p, g_attn_scratch);
        attn = (float*)p;
    }

    proj_qkv_kernel<<<dim3(HH / 64, M_PROJ / 64, 3), 256>>>(q, k, v, Wq, bq, Wk, bk, Wv, bv);
    scores_kernel<<<dim3(SS / 64, SS / 64, BH), 256>>>(mask, attn);
    softmax_kernel<<<BH * SS, 256>>>(attn);
    av_kernel<<<dim3(1, SS / 64, BH), 256>>>(attn);
    out_proj_kernel<<<dim3(HH / 64, M_PROJ / 64, 1), 256>>>(Wm, bm, out);
}